// round 1
// baseline (speedup 1.0000x reference)
#include <cuda_runtime.h>
#include <cstddef>

#define NUC 100000
#define NIC 50000
#define DC 64
#define LC 2
#define EBC 500000
#define ECC 1000000
#define EPC 2000000

// ---------------- scratch (device globals; no allocation allowed) ----------
__device__ float g_srcA[NUC * DC];
__device__ float g_srcB[NUC * DC];
__device__ float g_dstA[NIC * DC];
__device__ float g_dstB[NIC * DC];
__device__ float g_aggU[NUC * DC];
__device__ float g_aggV[NIC * DC];
__device__ float g_seU[NUC * DC];
__device__ float g_deV[NIC * DC];
__device__ float g_eb[(size_t)EBC * DC];   // 128 MB
__device__ float g_ec[(size_t)ECC * DC];   // 256 MB
__device__ float g_ep[(size_t)EPC * DC];   // 512 MB
__device__ float g_degU[3 * NUC];
__device__ float g_degV[3 * NIC];
__device__ float g_rsU[3 * NUC];
__device__ float g_rsV[3 * NIC];

__device__ __forceinline__ float lk(float x) { return x >= 0.f ? x : 0.01f * x; }

__device__ __forceinline__ void atomAdd4(float* p, float4 v) {
#if __CUDA_ARCH__ >= 900
    atomicAdd(reinterpret_cast<float4*>(p), v);
#else
    atomicAdd(p + 0, v.x); atomicAdd(p + 1, v.y);
    atomicAdd(p + 2, v.z); atomicAdd(p + 3, v.w);
#endif
}

// ---------------- kernels --------------------------------------------------

// buf = out = in * s (vectorized)
__global__ void k_init(const float4* __restrict__ in, float s,
                       float4* __restrict__ buf, float4* __restrict__ out, int n4) {
    int i = blockIdx.x * blockDim.x + threadIdx.x;
    if (i < n4) {
        float4 v = in[i];
        v.x *= s; v.y *= s; v.z *= s; v.w *= s;
        buf[i] = v; out[i] = v;
    }
}

__global__ void k_count(const int* __restrict__ U, const int* __restrict__ V, int E,
                        float* __restrict__ dU, float* __restrict__ dV) {
    int i = blockIdx.x * blockDim.x + threadIdx.x;
    if (i < E) {
        atomicAdd(dU + U[i], 1.f);
        atomicAdd(dV + V[i], 1.f);
    }
}

__global__ void k_findeg(float* __restrict__ deg, float* __restrict__ rs, int n) {
    int i = blockIdx.x * blockDim.x + threadIdx.x;
    if (i < n) {
        float d = deg[i];
        d = d < 1.f ? 1.f : d;
        deg[i] = d;
        rs[i] = rsqrtf(d);
    }
}

// Single fused edge read: gconv fwd msg scatter, gconv rev msg scatter,
// update_edge segment sums (se over u, de over v). 16 threads / edge, float4 lanes.
__global__ void k_pass1(const float* __restrict__ ew, float scale,
                        const int* __restrict__ U, const int* __restrict__ V,
                        const float* __restrict__ src, const float* __restrict__ dst,
                        const float* __restrict__ rsU, const float* __restrict__ rsV,
                        float* __restrict__ aggU, float* __restrict__ aggV,
                        float* __restrict__ seU, float* __restrict__ deV, int E) {
    long gid = (long)blockIdx.x * blockDim.x + threadIdx.x;
    int e = (int)(gid >> 4);
    int lane = (int)(gid & 15);
    if (e >= E) return;
    int u = U[e], v = V[e];
    float ru = rsU[u], rv = rsV[v];
    float4 w = *((const float4*)(ew + (size_t)e * DC) + lane);
    w.x *= scale; w.y *= scale; w.z *= scale; w.w *= scale;
    float4 s4 = *((const float4*)(src + (size_t)u * DC) + lane);
    float4 d4 = *((const float4*)(dst + (size_t)v * DC) + lane);
    float4 m1 = make_float4(s4.x * ru * w.x, s4.y * ru * w.y, s4.z * ru * w.z, s4.w * ru * w.w);
    float4 m2 = make_float4(d4.x * rv * w.x, d4.y * rv * w.y, d4.z * rv * w.z, d4.w * rv * w.w);
    atomAdd4(aggV + (size_t)v * DC + lane * 4, m1);   // forward gconv -> items
    atomAdd4(aggU + (size_t)u * DC + lane * 4, m2);   // reverse gconv -> users
    atomAdd4(seU  + (size_t)u * DC + lane * 4, w);    // update_edge seg-sum over u
    atomAdd4(deV  + (size_t)v * DC + lane * 4, w);    // update_edge seg-sum over v
}

// out[row] (op)= wgt * leaky((agg[row] @ W) * rs[row]) ; store=1 writes, else accumulates
__global__ void k_node_gconv(const float* __restrict__ agg, const float* __restrict__ W,
                             const float* __restrict__ rs, float wgt,
                             float* __restrict__ out, int N, int store) {
    __shared__ float sW[DC * DC];
    __shared__ float srow[4][DC];
    for (int i = threadIdx.x; i < DC * DC; i += blockDim.x) sW[i] = W[i];
    int rb = threadIdx.x >> 6, k = threadIdx.x & 63;
    int row = blockIdx.x * 4 + rb;
    if (row < N) srow[rb][k] = agg[(size_t)row * DC + k];
    __syncthreads();
    if (row < N) {
        float acc = 0.f;
#pragma unroll
        for (int d = 0; d < DC; d++) acc = fmaf(srow[rb][d], sW[d * DC + k], acc);
        acc *= rs[row];
        acc = lk(acc);
        acc *= wgt;
        size_t o = (size_t)row * DC + k;
        out[o] = store ? acc : (out[o] + acc);
    }
}

// buf[row] = buf[row] @ W (in place; row read fully before written)
__global__ void k_node_mm(float* __restrict__ buf, const float* __restrict__ W, int N) {
    __shared__ float sW[DC * DC];
    __shared__ float srow[4][DC];
    for (int i = threadIdx.x; i < DC * DC; i += blockDim.x) sW[i] = W[i];
    int rb = threadIdx.x >> 6, k = threadIdx.x & 63;
    int row = blockIdx.x * 4 + rb;
    if (row < N) srow[rb][k] = buf[(size_t)row * DC + k];
    __syncthreads();
    if (row < N) {
        float acc = 0.f;
#pragma unroll
        for (int d = 0; d < DC; d++) acc = fmaf(srow[rb][d], sW[d * DC + k], acc);
        buf[(size_t)row * DC + k] = acc;
    }
}

// new_edge[e] = leaky((seW[u] + deW[v]) / (degU[u] + degV[v]))
// (scalar division commutes with @W, so the 64x64 matmul was hoisted to node level)
__global__ void k_pass2(float* __restrict__ eout,
                        const int* __restrict__ U, const int* __restrict__ V,
                        const float* __restrict__ seW, const float* __restrict__ deW,
                        const float* __restrict__ dU, const float* __restrict__ dV, int E) {
    long gid = (long)blockIdx.x * blockDim.x + threadIdx.x;
    int e = (int)(gid >> 4);
    int lane = (int)(gid & 15);
    if (e >= E) return;
    int u = U[e], v = V[e];
    float s = 1.f / (dU[u] + dV[v]);
    float4 a = *((const float4*)(seW + (size_t)u * DC) + lane);
    float4 b = *((const float4*)(deW + (size_t)v * DC) + lane);
    float4 t;
    t.x = lk((a.x + b.x) * s);
    t.y = lk((a.y + b.y) * s);
    t.z = lk((a.z + b.z) * s);
    t.w = lk((a.w + b.w) * s);
    *((float4*)(eout + (size_t)e * DC) + lane) = t;
}

__global__ void k_axpy(float4* __restrict__ out, const float4* __restrict__ x, int n4) {
    int i = blockIdx.x * blockDim.x + threadIdx.x;
    if (i < n4) {
        float4 o = out[i], v = x[i];
        o.x += v.x; o.y += v.y; o.z += v.z; o.w += v.w;
        out[i] = o;
    }
}

__global__ void k_scale(float4* __restrict__ out, float s, int n4) {
    int i = blockIdx.x * blockDim.x + threadIdx.x;
    if (i < n4) {
        float4 o = out[i];
        o.x *= s; o.y *= s; o.z *= s; o.w *= s;
        out[i] = o;
    }
}

// ---------------- host orchestration ---------------------------------------
extern "C" void kernel_launch(void* const* d_in, const int* in_sizes, int n_in,
                              void* d_out, int out_size) {
    const float* user_emb = (const float*)d_in[0];
    const float* item_emb = (const float*)d_in[1];
    const float* ebi = (const float*)d_in[2];
    const float* eci = (const float*)d_in[3];
    const float* epi = (const float*)d_in[4];
    const float* nodeW = (const float*)d_in[5];
    const float* edgeW = (const float*)d_in[6];
    const int* bu = (const int*)d_in[7];
    const int* bv = (const int*)d_in[8];
    const int* cu = (const int*)d_in[9];
    const int* cv = (const int*)d_in[10];
    const int* pu = (const int*)d_in[11];
    const int* pvv = (const int*)d_in[12];
    float* out = (float*)d_out;
    float* outS = out;
    float* outD = out + (size_t)NUC * DC;

    float *srcA, *srcB, *dstA, *dstB, *aggU, *aggV, *seU, *deV, *eb, *ec, *ep;
    float *degU, *degV, *rsU, *rsV;
    cudaGetSymbolAddress((void**)&srcA, g_srcA);
    cudaGetSymbolAddress((void**)&srcB, g_srcB);
    cudaGetSymbolAddress((void**)&dstA, g_dstA);
    cudaGetSymbolAddress((void**)&dstB, g_dstB);
    cudaGetSymbolAddress((void**)&aggU, g_aggU);
    cudaGetSymbolAddress((void**)&aggV, g_aggV);
    cudaGetSymbolAddress((void**)&seU, g_seU);
    cudaGetSymbolAddress((void**)&deV, g_deV);
    cudaGetSymbolAddress((void**)&eb, g_eb);
    cudaGetSymbolAddress((void**)&ec, g_ec);
    cudaGetSymbolAddress((void**)&ep, g_ep);
    cudaGetSymbolAddress((void**)&degU, g_degU);
    cudaGetSymbolAddress((void**)&degV, g_degV);
    cudaGetSymbolAddress((void**)&rsU, g_rsU);
    cudaGetSymbolAddress((void**)&rsV, g_rsV);

    const float Asc = 0.0045f, Bsc = 0.0045f;

    // init node features + output accumulators
    {
        int n4 = NUC * DC / 4;
        k_init<<<(n4 + 255) / 256, 256>>>((const float4*)user_emb, Asc,
                                          (float4*)srcA, (float4*)outS, n4);
        int m4 = NIC * DC / 4;
        k_init<<<(m4 + 255) / 256, 256>>>((const float4*)item_emb, Asc,
                                          (float4*)dstA, (float4*)outD, m4);
    }

    // degrees + inverse-sqrt norms (recomputed every call: determinism rule)
    cudaMemsetAsync(degU, 0, (size_t)3 * NUC * sizeof(float));
    cudaMemsetAsync(degV, 0, (size_t)3 * NIC * sizeof(float));
    k_count<<<(EBC + 255) / 256, 256>>>(bu, bv, EBC, degU + 0 * NUC, degV + 0 * NIC);
    k_count<<<(ECC + 255) / 256, 256>>>(cu, cv, ECC, degU + 1 * NUC, degV + 1 * NIC);
    k_count<<<(EPC + 255) / 256, 256>>>(pu, pvv, EPC, degU + 2 * NUC, degV + 2 * NIC);
    for (int t = 0; t < 3; t++) {
        k_findeg<<<(NUC + 255) / 256, 256>>>(degU + t * NUC, rsU + t * NUC, NUC);
        k_findeg<<<(NIC + 255) / 256, 256>>>(degV + t * NIC, rsV + t * NIC, NIC);
    }

    const int* Ua[3] = {bu, cu, pu};
    const int* Va[3] = {bv, cv, pvv};
    const float* Ein[3] = {ebi, eci, epi};
    float* Ebuf[3] = {eb, ec, ep};
    const int Ecnt[3] = {EBC, ECC, EPC};
    const float wgt[3] = {1.0f, 0.5f, 0.25f};

    float* sCur = srcA; float* sNext = srcB;
    float* dCur = dstA; float* dNext = dstB;

    for (int layer = 0; layer < LC; ++layer) {
        const float* Wn = nodeW + (size_t)layer * DC * DC;
        const float* We = edgeW + (size_t)layer * DC * DC;
        for (int t = 0; t < 3; t++) {
            cudaMemsetAsync(aggU, 0, (size_t)NUC * DC * sizeof(float));
            cudaMemsetAsync(aggV, 0, (size_t)NIC * DC * sizeof(float));
            cudaMemsetAsync(seU, 0, (size_t)NUC * DC * sizeof(float));
            cudaMemsetAsync(deV, 0, (size_t)NIC * DC * sizeof(float));

            const float* esrc = (layer == 0) ? Ein[t] : Ebuf[t];
            float escale = (layer == 0) ? Bsc : 1.0f;
            long threads = (long)Ecnt[t] * 16;
            int blocks = (int)((threads + 255) / 256);

            k_pass1<<<blocks, 256>>>(esrc, escale, Ua[t], Va[t], sCur, dCur,
                                     rsU + t * NUC, rsV + t * NIC,
                                     aggU, aggV, seU, deV, Ecnt[t]);

            k_node_gconv<<<(NIC + 3) / 4, 256>>>(aggV, Wn, rsV + t * NIC, wgt[t],
                                                 dNext, NIC, t == 0 ? 1 : 0);
            k_node_gconv<<<(NUC + 3) / 4, 256>>>(aggU, Wn, rsU + t * NUC, wgt[t],
                                                 sNext, NUC, t == 0 ? 1 : 0);

            // hoisted update_edge matmul: se@We, de@We at node granularity
            k_node_mm<<<(NUC + 3) / 4, 256>>>(seU, We, NUC);
            k_node_mm<<<(NIC + 3) / 4, 256>>>(deV, We, NIC);

            k_pass2<<<blocks, 256>>>(Ebuf[t], Ua[t], Va[t], seU, deV,
                                     degU + t * NUC, degV + t * NIC, Ecnt[t]);
        }
        k_axpy<<<(NUC * DC / 4 + 255) / 256, 256>>>((float4*)outS, (const float4*)sNext, NUC * DC / 4);
        k_axpy<<<(NIC * DC / 4 + 255) / 256, 256>>>((float4*)outD, (const float4*)dNext, NIC * DC / 4);

        float* tmp;
        tmp = sCur; sCur = sNext; sNext = tmp;
        tmp = dCur; dCur = dNext; dNext = tmp;
    }

    int total4 = (NUC + NIC) * DC / 4;
    k_scale<<<(total4 + 255) / 256, 256>>>((float4*)out, 1.f / 3.f, total4);
}

// round 2
// speedup vs baseline: 1.5343x; 1.5343x over previous
#include <cuda_runtime.h>
#include <cstddef>

#define NUC 100000
#define NIC 50000
#define DC 64
#define EBC 500000
#define ECC 1000000
#define EPC 2000000

// ---------------- scratch (device globals; no allocation allowed) ----------
__device__ float g_srcA[NUC * DC];
__device__ float g_srcB[NUC * DC];
__device__ float g_dstA[NIC * DC];
__device__ float g_dstB[NIC * DC];
__device__ float g_aggU[NUC * DC];
__device__ float g_aggV[NIC * DC];
__device__ float g_seU[3][NUC * DC];   // per-type update_edge u-side sums (-> @We)
__device__ float g_deV[3][NIC * DC];   // per-type update_edge v-side sums (-> @We)
__device__ float g_degU[3 * NUC];
__device__ float g_degV[3 * NIC];
__device__ float g_rsU[3 * NUC];
__device__ float g_rsV[3 * NIC];

__device__ __forceinline__ float lk(float x) { return x >= 0.f ? x : 0.01f * x; }

__device__ __forceinline__ void atomAdd4(float* p, float4 v) {
    atomicAdd(reinterpret_cast<float4*>(p), v);
}

// ---------------- kernels --------------------------------------------------

// buf = in*s ; out = in*s/3 (output accumulator pre-scaled by final 1/(L+1))
__global__ void k_init(const float4* __restrict__ in, float s,
                       float4* __restrict__ buf, float4* __restrict__ out, int n4) {
    int i = blockIdx.x * blockDim.x + threadIdx.x;
    if (i < n4) {
        float4 v = in[i];
        v.x *= s; v.y *= s; v.z *= s; v.w *= s;
        buf[i] = v;
        float4 o = make_float4(v.x * (1.f / 3.f), v.y * (1.f / 3.f),
                               v.z * (1.f / 3.f), v.w * (1.f / 3.f));
        out[i] = o;
    }
}

__global__ void k_count(const int* __restrict__ U, const int* __restrict__ V, int E,
                        float* __restrict__ dU, float* __restrict__ dV) {
    int i = blockIdx.x * blockDim.x + threadIdx.x;
    if (i < E) {
        atomicAdd(dU + U[i], 1.f);
        atomicAdd(dV + V[i], 1.f);
    }
}

__global__ void k_findeg(float* __restrict__ deg, float* __restrict__ rs, int n) {
    int i = blockIdx.x * blockDim.x + threadIdx.x;
    if (i < n) {
        float d = deg[i];
        d = d < 1.f ? 1.f : d;
        deg[i] = d;
        rs[i] = rsqrtf(d);
    }
}

// Layer-0 edge pass: ONE read of the input edge stream feeds both gconv message
// scatters AND the update_edge segment sums. 16 threads/edge, float4 lanes.
__global__ void k_pass1_l0(const float* __restrict__ ew, float scale,
                           const int* __restrict__ U, const int* __restrict__ V,
                           const float* __restrict__ src, const float* __restrict__ dst,
                           const float* __restrict__ rsU, const float* __restrict__ rsV,
                           float* __restrict__ aggU, float* __restrict__ aggV,
                           float* __restrict__ se, float* __restrict__ de, int E) {
    long gid = (long)blockIdx.x * blockDim.x + threadIdx.x;
    int e = (int)(gid >> 4);
    int lane = (int)(gid & 15);
    if (e >= E) return;
    int u = U[e], v = V[e];
    float ru = rsU[u], rv = rsV[v];
    float4 w = *((const float4*)(ew + (size_t)e * DC) + lane);
    w.x *= scale; w.y *= scale; w.z *= scale; w.w *= scale;
    float4 s4 = *((const float4*)(src + (size_t)u * DC) + lane);
    float4 d4 = *((const float4*)(dst + (size_t)v * DC) + lane);
    float4 m1 = make_float4(s4.x * ru * w.x, s4.y * ru * w.y, s4.z * ru * w.z, s4.w * ru * w.w);
    float4 m2 = make_float4(d4.x * rv * w.x, d4.y * rv * w.y, d4.z * rv * w.z, d4.w * rv * w.w);
    atomAdd4(aggV + (size_t)v * DC + lane * 4, m1);
    atomAdd4(aggU + (size_t)u * DC + lane * 4, m2);
    atomAdd4(se + (size_t)u * DC + lane * 4, w);
    atomAdd4(de + (size_t)v * DC + lane * 4, w);
}

// Layer-1 edge pass, FUSED with layer-0's update_edge: the layer-1 edge feature
//   e = leaky((seW[u] + deW[v]) / (degU[u] + degV[v]))
// is materialized in registers only — the 896 MB/layer edge buffer round-trip
// is eliminated. Final-layer update_edge is dead code, so no se/de scatters.
__global__ void k_pass_l1(const int* __restrict__ U, const int* __restrict__ V,
                          const float* __restrict__ seW, const float* __restrict__ deW,
                          const float* __restrict__ dU, const float* __restrict__ dV,
                          const float* __restrict__ src, const float* __restrict__ dst,
                          const float* __restrict__ rsU, const float* __restrict__ rsV,
                          float* __restrict__ aggU, float* __restrict__ aggV, int E) {
    long gid = (long)blockIdx.x * blockDim.x + threadIdx.x;
    int e = (int)(gid >> 4);
    int lane = (int)(gid & 15);
    if (e >= E) return;
    int u = U[e], v = V[e];
    float s = 1.f / (dU[u] + dV[v]);
    float ru = rsU[u], rv = rsV[v];
    float4 a = *((const float4*)(seW + (size_t)u * DC) + lane);
    float4 b = *((const float4*)(deW + (size_t)v * DC) + lane);
    float4 w;
    w.x = lk((a.x + b.x) * s);
    w.y = lk((a.y + b.y) * s);
    w.z = lk((a.z + b.z) * s);
    w.w = lk((a.w + b.w) * s);
    float4 s4 = *((const float4*)(src + (size_t)u * DC) + lane);
    float4 d4 = *((const float4*)(dst + (size_t)v * DC) + lane);
    float4 m1 = make_float4(s4.x * ru * w.x, s4.y * ru * w.y, s4.z * ru * w.z, s4.w * ru * w.w);
    float4 m2 = make_float4(d4.x * rv * w.x, d4.y * rv * w.y, d4.z * rv * w.z, d4.w * rv * w.w);
    atomAdd4(aggV + (size_t)v * DC + lane * 4, m1);
    atomAdd4(aggU + (size_t)u * DC + lane * 4, m2);
}

// nxt[row] (op)= wgt * leaky((agg[row] @ W) * rs[row])
// mode 0: store. mode 1: accumulate. mode 2: accumulate + emit total/3 into out.
__global__ void k_node_gconv(const float* __restrict__ agg, const float* __restrict__ W,
                             const float* __restrict__ rs, float wgt,
                             float* __restrict__ nxt, float* __restrict__ outp,
                             int N, int mode) {
    __shared__ float sW[DC * DC];
    __shared__ float srow[4][DC];
    for (int i = threadIdx.x; i < DC * DC; i += blockDim.x) sW[i] = W[i];
    int rb = threadIdx.x >> 6, k = threadIdx.x & 63;
    int row = blockIdx.x * 4 + rb;
    if (row < N) srow[rb][k] = agg[(size_t)row * DC + k];
    __syncthreads();
    if (row < N) {
        float acc = 0.f;
#pragma unroll
        for (int d = 0; d < DC; d++) acc = fmaf(srow[rb][d], sW[d * DC + k], acc);
        acc *= rs[row];
        acc = lk(acc);
        acc *= wgt;
        size_t o = (size_t)row * DC + k;
        if (mode == 0) {
            nxt[o] = acc;
        } else if (mode == 1) {
            nxt[o] += acc;
        } else {
            float tot = nxt[o] + acc;
            nxt[o] = tot;
            outp[o] += tot * (1.f / 3.f);
        }
    }
}

// buf[row] = buf[row] @ W (in place)
__global__ void k_node_mm(float* __restrict__ buf, const float* __restrict__ W, int N) {
    __shared__ float sW[DC * DC];
    __shared__ float srow[4][DC];
    for (int i = threadIdx.x; i < DC * DC; i += blockDim.x) sW[i] = W[i];
    int rb = threadIdx.x >> 6, k = threadIdx.x & 63;
    int row = blockIdx.x * 4 + rb;
    if (row < N) srow[rb][k] = buf[(size_t)row * DC + k];
    __syncthreads();
    if (row < N) {
        float acc = 0.f;
#pragma unroll
        for (int d = 0; d < DC; d++) acc = fmaf(srow[rb][d], sW[d * DC + k], acc);
        buf[(size_t)row * DC + k] = acc;
    }
}

// ---------------- host orchestration ---------------------------------------
extern "C" void kernel_launch(void* const* d_in, const int* in_sizes, int n_in,
                              void* d_out, int out_size) {
    const float* user_emb = (const float*)d_in[0];
    const float* item_emb = (const float*)d_in[1];
    const float* ebi = (const float*)d_in[2];
    const float* eci = (const float*)d_in[3];
    const float* epi = (const float*)d_in[4];
    const float* nodeW = (const float*)d_in[5];
    const float* edgeW = (const float*)d_in[6];
    const int* bu = (const int*)d_in[7];
    const int* bv = (const int*)d_in[8];
    const int* cu = (const int*)d_in[9];
    const int* cv = (const int*)d_in[10];
    const int* pu = (const int*)d_in[11];
    const int* pvv = (const int*)d_in[12];
    float* out = (float*)d_out;
    float* outS = out;
    float* outD = out + (size_t)NUC * DC;

    float *srcA, *srcB, *dstA, *dstB, *aggU, *aggV;
    float *seBase, *deBase, *degU, *degV, *rsU, *rsV;
    cudaGetSymbolAddress((void**)&srcA, g_srcA);
    cudaGetSymbolAddress((void**)&srcB, g_srcB);
    cudaGetSymbolAddress((void**)&dstA, g_dstA);
    cudaGetSymbolAddress((void**)&dstB, g_dstB);
    cudaGetSymbolAddress((void**)&aggU, g_aggU);
    cudaGetSymbolAddress((void**)&aggV, g_aggV);
    cudaGetSymbolAddress((void**)&seBase, g_seU);
    cudaGetSymbolAddress((void**)&deBase, g_deV);
    cudaGetSymbolAddress((void**)&degU, g_degU);
    cudaGetSymbolAddress((void**)&degV, g_degV);
    cudaGetSymbolAddress((void**)&rsU, g_rsU);
    cudaGetSymbolAddress((void**)&rsV, g_rsV);

    const float Asc = 0.0045f, Bsc = 0.0045f;

    // init node features + output accumulators (out pre-scaled by 1/3)
    {
        int n4 = NUC * DC / 4;
        k_init<<<(n4 + 255) / 256, 256>>>((const float4*)user_emb, Asc,
                                          (float4*)srcA, (float4*)outS, n4);
        int m4 = NIC * DC / 4;
        k_init<<<(m4 + 255) / 256, 256>>>((const float4*)item_emb, Asc,
                                          (float4*)dstA, (float4*)outD, m4);
    }

    // degrees + inverse-sqrt norms (recomputed every call: determinism rule)
    cudaMemsetAsync(degU, 0, (size_t)3 * NUC * sizeof(float));
    cudaMemsetAsync(degV, 0, (size_t)3 * NIC * sizeof(float));
    k_count<<<(EBC + 255) / 256, 256>>>(bu, bv, EBC, degU + 0 * NUC, degV + 0 * NIC);
    k_count<<<(ECC + 255) / 256, 256>>>(cu, cv, ECC, degU + 1 * NUC, degV + 1 * NIC);
    k_count<<<(EPC + 255) / 256, 256>>>(pu, pvv, EPC, degU + 2 * NUC, degV + 2 * NIC);
    for (int t = 0; t < 3; t++) {
        k_findeg<<<(NUC + 255) / 256, 256>>>(degU + t * NUC, rsU + t * NUC, NUC);
        k_findeg<<<(NIC + 255) / 256, 256>>>(degV + t * NIC, rsV + t * NIC, NIC);
    }

    const int* Ua[3] = {bu, cu, pu};
    const int* Va[3] = {bv, cv, pvv};
    const float* Ein[3] = {ebi, eci, epi};
    const int Ecnt[3] = {EBC, ECC, EPC};
    const float wgt[3] = {1.0f, 0.5f, 0.25f};

    const float* Wn0 = nodeW;
    const float* Wn1 = nodeW + (size_t)DC * DC;
    const float* We0 = edgeW;

    // ---------------- layer 0 ----------------
    for (int t = 0; t < 3; t++) {
        float* se = seBase + (size_t)t * NUC * DC;
        float* de = deBase + (size_t)t * NIC * DC;
        cudaMemsetAsync(aggU, 0, (size_t)NUC * DC * sizeof(float));
        cudaMemsetAsync(aggV, 0, (size_t)NIC * DC * sizeof(float));
        cudaMemsetAsync(se, 0, (size_t)NUC * DC * sizeof(float));
        cudaMemsetAsync(de, 0, (size_t)NIC * DC * sizeof(float));

        long threads = (long)Ecnt[t] * 16;
        int blocks = (int)((threads + 255) / 256);
        k_pass1_l0<<<blocks, 256>>>(Ein[t], Bsc, Ua[t], Va[t], srcA, dstA,
                                    rsU + t * NUC, rsV + t * NIC,
                                    aggU, aggV, se, de, Ecnt[t]);

        k_node_gconv<<<(NIC + 3) / 4, 256>>>(aggV, Wn0, rsV + t * NIC, wgt[t],
                                             dstB, outD, NIC, t == 0 ? 0 : (t == 2 ? 2 : 1));
        k_node_gconv<<<(NUC + 3) / 4, 256>>>(aggU, Wn0, rsU + t * NUC, wgt[t],
                                             srcB, outS, NUC, t == 0 ? 0 : (t == 2 ? 2 : 1));

        // hoisted update_edge matmul at node granularity: se <- se@We0, de <- de@We0
        k_node_mm<<<(NUC + 3) / 4, 256>>>(se, We0, NUC);
        k_node_mm<<<(NIC + 3) / 4, 256>>>(de, We0, NIC);
    }

    // ---------------- layer 1 (fused edge-feature recompute, no edge buffers) --
    for (int t = 0; t < 3; t++) {
        float* se = seBase + (size_t)t * NUC * DC;
        float* de = deBase + (size_t)t * NIC * DC;
        cudaMemsetAsync(aggU, 0, (size_t)NUC * DC * sizeof(float));
        cudaMemsetAsync(aggV, 0, (size_t)NIC * DC * sizeof(float));

        long threads = (long)Ecnt[t] * 16;
        int blocks = (int)((threads + 255) / 256);
        k_pass_l1<<<blocks, 256>>>(Ua[t], Va[t], se, de,
                                   degU + t * NUC, degV + t * NIC,
                                   srcB, dstB, rsU + t * NUC, rsV + t * NIC,
                                   aggU, aggV, Ecnt[t]);

        k_node_gconv<<<(NIC + 3) / 4, 256>>>(aggV, Wn1, rsV + t * NIC, wgt[t],
                                             dstA, outD, NIC, t == 0 ? 0 : (t == 2 ? 2 : 1));
        k_node_gconv<<<(NUC + 3) / 4, 256>>>(aggU, Wn1, rsU + t * NUC, wgt[t],
                                             srcA, outS, NUC, t == 0 ? 0 : (t == 2 ? 2 : 1));
    }
}

// round 4
// speedup vs baseline: 2.1079x; 1.3739x over previous
#include <cuda_runtime.h>
#include <cstddef>

#define NUC 100000
#define NIC 50000
#define DC 64
#define EBC 500000
#define ECC 1000000
#define EPC 2000000
#define ETOT (EBC + ECC + EPC)

// ---------------- scratch (device globals; no allocation allowed) ----------
__device__ float g_srcA[NUC * DC];
__device__ float g_srcB[NUC * DC];
__device__ float g_dstA[NIC * DC];
__device__ float g_dstB[NIC * DC];
__device__ float g_aggU[3][NUC * DC];
__device__ float g_aggV[3][NIC * DC];
__device__ float g_se[3][NUC * DC];
__device__ float g_de[3][NIC * DC];
__device__ int g_cntU[3 * NUC];
__device__ int g_cntV[3 * NIC];
__device__ int g_rowU[3 * (NUC + 1)];
__device__ int g_rowV[3 * (NIC + 1)];
__device__ int g_curU[3 * NUC];
__device__ int g_curV[3 * NIC];
__device__ float g_degU[3 * NUC];
__device__ float g_degV[3 * NIC];
__device__ float g_rsU[3 * NUC];
__device__ float g_rsV[3 * NIC];
__device__ int2 g_adjU[ETOT];   // {edge id, opposite node}
__device__ int2 g_adjV[ETOT];

__device__ __forceinline__ float lk(float x) { return x >= 0.f ? x : 0.01f * x; }

// ---------------- setup kernels --------------------------------------------

// buf = in*s ; out = in*s/3 (output accumulator pre-scaled by final 1/(L+1))
__global__ void k_init(const float4* __restrict__ in, float s,
                       float4* __restrict__ buf, float4* __restrict__ out, int n4) {
    int i = blockIdx.x * blockDim.x + threadIdx.x;
    if (i < n4) {
        float4 v = in[i];
        v.x *= s; v.y *= s; v.z *= s; v.w *= s;
        buf[i] = v;
        out[i] = make_float4(v.x * (1.f / 3.f), v.y * (1.f / 3.f),
                             v.z * (1.f / 3.f), v.w * (1.f / 3.f));
    }
}

__global__ void k_hist(const int* __restrict__ U, const int* __restrict__ V, int E,
                       int* __restrict__ cU, int* __restrict__ cV) {
    int i = blockIdx.x * blockDim.x + threadIdx.x;
    if (i < E) {
        atomicAdd(cU + U[i], 1);
        atomicAdd(cV + V[i], 1);
    }
}

__global__ void k_deg(const int* __restrict__ cnt, float* __restrict__ deg,
                      float* __restrict__ rs, int n) {
    int i = blockIdx.x * blockDim.x + threadIdx.x;
    if (i < n) {
        float d = (float)(cnt[i] < 1 ? 1 : cnt[i]);
        deg[i] = d;
        rs[i] = rsqrtf(d);
    }
}

// 6 blocks: block b handles (side=b/3, type=b%3). Exclusive scan of counts into
// row offsets; also initializes fill cursors and writes row[n] = total.
__global__ void k_scan6(const int* __restrict__ cntU, const int* __restrict__ cntV,
                        int* __restrict__ rowU, int* __restrict__ rowV,
                        int* __restrict__ curU, int* __restrict__ curV) {
    __shared__ int ssum[1024];
    int b = blockIdx.x, side = b / 3, t = b % 3;
    const int* cnt; int* row; int* cur; int n;
    if (side == 0) { n = NUC; cnt = cntU + t * NUC; row = rowU + t * (NUC + 1); cur = curU + t * NUC; }
    else           { n = NIC; cnt = cntV + t * NIC; row = rowV + t * (NIC + 1); cur = curV + t * NIC; }
    int tid = threadIdx.x;
    int chunk = (n + 1023) / 1024;
    int lo = tid * chunk; if (lo > n) lo = n;
    int hi = lo + chunk; if (hi > n) hi = n;
    int s = 0;
    for (int i = lo; i < hi; i++) s += cnt[i];
    ssum[tid] = s;
    __syncthreads();
    for (int off = 1; off < 1024; off <<= 1) {
        int v = (tid >= off) ? ssum[tid - off] : 0;
        __syncthreads();
        ssum[tid] += v;
        __syncthreads();
    }
    int run = (tid == 0) ? 0 : ssum[tid - 1];
    for (int i = lo; i < hi; i++) {
        row[i] = run; cur[i] = run;
        run += cnt[i];
    }
    if (hi == n) row[n] = run;  // all threads past the end agree: run == total
}

__global__ void k_fill(const int* __restrict__ U, const int* __restrict__ V, int E,
                       int* __restrict__ cU, int* __restrict__ cV,
                       int2* __restrict__ adjU, int2* __restrict__ adjV) {
    int e = blockIdx.x * blockDim.x + threadIdx.x;
    if (e < E) {
        int u = U[e], v = V[e];
        int pu = atomicAdd(cU + u, 1);
        adjU[pu] = make_int2(e, v);
        int pv = atomicAdd(cV + v, 1);
        adjV[pv] = make_int2(e, u);
    }
}

// ---------------- gather kernels (warp per node, 16 lanes x 2 edges) --------

// Layer 0: agg[node] = sum_e oppF[opp]*rsOpp[opp]*w_e ; ssum[node] = sum_e w_e
__global__ void k_gather_l0(const int2* __restrict__ adj, const int* __restrict__ row,
                            const float* __restrict__ ew, float scale,
                            const float* __restrict__ oppF, const float* __restrict__ rsOpp,
                            float* __restrict__ agg, float* __restrict__ ssum, int n) {
    int node = (blockIdx.x * blockDim.x + threadIdx.x) >> 5;
    if (node >= n) return;
    int lane = threadIdx.x & 31;
    int l16 = lane & 15, half = lane >> 4;
    int s0 = row[node], s1 = row[node + 1];
    float4 a = make_float4(0.f, 0.f, 0.f, 0.f);
    float4 b = make_float4(0.f, 0.f, 0.f, 0.f);
    for (int i = s0 + half; i < s1; i += 2) {
        int2 ad = __ldg(adj + i);
        float4 w = __ldg((const float4*)(ew + (size_t)ad.x * DC) + l16);
        float r = __ldg(rsOpp + ad.y);
        float4 f = __ldg((const float4*)(oppF + (size_t)ad.y * DC) + l16);
        w.x *= scale; w.y *= scale; w.z *= scale; w.w *= scale;
        b.x += w.x; b.y += w.y; b.z += w.z; b.w += w.w;
        a.x += f.x * r * w.x; a.y += f.y * r * w.y;
        a.z += f.z * r * w.z; a.w += f.w * r * w.w;
    }
    a.x += __shfl_xor_sync(0xffffffffu, a.x, 16);
    a.y += __shfl_xor_sync(0xffffffffu, a.y, 16);
    a.z += __shfl_xor_sync(0xffffffffu, a.z, 16);
    a.w += __shfl_xor_sync(0xffffffffu, a.w, 16);
    b.x += __shfl_xor_sync(0xffffffffu, b.x, 16);
    b.y += __shfl_xor_sync(0xffffffffu, b.y, 16);
    b.z += __shfl_xor_sync(0xffffffffu, b.z, 16);
    b.w += __shfl_xor_sync(0xffffffffu, b.w, 16);
    if (half == 0) {
        ((float4*)(agg + (size_t)node * DC))[l16] = a;
        ((float4*)(ssum + (size_t)node * DC))[l16] = b;
    }
}

// Layer 1: edge weight recomputed on the fly from node-level update_edge data:
//   w_e = leaky((myDeW[node] + oppDeW[opp]) / (myDeg[node] + oppDeg[opp]))
// agg[node] = sum_e oppF[opp]*rsOpp[opp]*w_e
__global__ void k_gather_l1(const int2* __restrict__ adj, const int* __restrict__ row,
                            const float* __restrict__ myDeW, const float* __restrict__ oppDeW,
                            const float* __restrict__ myDeg, const float* __restrict__ oppDeg,
                            const float* __restrict__ oppF, const float* __restrict__ rsOpp,
                            float* __restrict__ agg, int n) {
    int node = (blockIdx.x * blockDim.x + threadIdx.x) >> 5;
    if (node >= n) return;
    int lane = threadIdx.x & 31;
    int l16 = lane & 15, half = lane >> 4;
    int s0 = row[node], s1 = row[node + 1];
    float md = myDeg[node];
    float4 m = ((const float4*)(myDeW + (size_t)node * DC))[l16];
    float4 a = make_float4(0.f, 0.f, 0.f, 0.f);
    for (int i = s0 + half; i < s1; i += 2) {
        int2 ad = __ldg(adj + i);
        float od = __ldg(oppDeg + ad.y);
        float s = 1.f / (md + od);
        float4 o = __ldg((const float4*)(oppDeW + (size_t)ad.y * DC) + l16);
        float r = __ldg(rsOpp + ad.y);
        float4 f = __ldg((const float4*)(oppF + (size_t)ad.y * DC) + l16);
        float wx = lk((m.x + o.x) * s);
        float wy = lk((m.y + o.y) * s);
        float wz = lk((m.z + o.z) * s);
        float ww = lk((m.w + o.w) * s);
        a.x += f.x * r * wx; a.y += f.y * r * wy;
        a.z += f.z * r * wz; a.w += f.w * r * ww;
    }
    a.x += __shfl_xor_sync(0xffffffffu, a.x, 16);
    a.y += __shfl_xor_sync(0xffffffffu, a.y, 16);
    a.z += __shfl_xor_sync(0xffffffffu, a.z, 16);
    a.w += __shfl_xor_sync(0xffffffffu, a.w, 16);
    if (half == 0)
        ((float4*)(agg + (size_t)node * DC))[l16] = a;
}

// ---------------- node matmul kernels ---------------------------------------

// Fused 3-type gconv epilogue over 16 rows/block:
//   res = 1*lk((agg0@W)*rs0) + 0.5*lk((agg1@W)*rs1) + 0.25*lk((agg2@W)*rs2)
//   nxt[row]=res (optional) ; outp[row] += res/3
__global__ void k_gconv3(const float* __restrict__ agg, size_t aggStride,
                         const float* __restrict__ W,
                         const float* __restrict__ rs, int rsStride,
                         float* __restrict__ nxt, float* __restrict__ outp,
                         int N, int writeNxt) {
    __shared__ float4 sW4[64 * 16];
    __shared__ float srow[3][16][68];
    int tid = threadIdx.x;
    int ty = tid >> 4, k4 = tid & 15;
    for (int i = tid; i < 1024; i += 256) sW4[i] = ((const float4*)W)[i];
    int r = blockIdx.x * 16 + ty;
    if (r < N) {
#pragma unroll
        for (int t = 0; t < 3; t++) {
            float4 v = ((const float4*)(agg + t * aggStride + (size_t)r * DC))[k4];
            srow[t][ty][k4 * 4 + 0] = v.x;
            srow[t][ty][k4 * 4 + 1] = v.y;
            srow[t][ty][k4 * 4 + 2] = v.z;
            srow[t][ty][k4 * 4 + 3] = v.w;
        }
    }
    __syncthreads();
    if (r >= N) return;
    float4 a0 = make_float4(0.f, 0.f, 0.f, 0.f);
    float4 a1 = make_float4(0.f, 0.f, 0.f, 0.f);
    float4 a2 = make_float4(0.f, 0.f, 0.f, 0.f);
#pragma unroll
    for (int d = 0; d < 64; d++) {
        float4 w4 = sW4[d * 16 + k4];
        float s0 = srow[0][ty][d], s1 = srow[1][ty][d], s2 = srow[2][ty][d];
        a0.x += s0 * w4.x; a0.y += s0 * w4.y; a0.z += s0 * w4.z; a0.w += s0 * w4.w;
        a1.x += s1 * w4.x; a1.y += s1 * w4.y; a1.z += s1 * w4.z; a1.w += s1 * w4.w;
        a2.x += s2 * w4.x; a2.y += s2 * w4.y; a2.z += s2 * w4.z; a2.w += s2 * w4.w;
    }
    float r0 = rs[r], r1 = rs[rsStride + r], r2 = rs[2 * rsStride + r];
    float4 res;
    res.x = lk(a0.x * r0) + 0.5f * lk(a1.x * r1) + 0.25f * lk(a2.x * r2);
    res.y = lk(a0.y * r0) + 0.5f * lk(a1.y * r1) + 0.25f * lk(a2.y * r2);
    res.z = lk(a0.z * r0) + 0.5f * lk(a1.z * r1) + 0.25f * lk(a2.z * r2);
    res.w = lk(a0.w * r0) + 0.5f * lk(a1.w * r1) + 0.25f * lk(a2.w * r2);
    size_t off = (size_t)r * DC;
    if (writeNxt) ((float4*)(nxt + off))[k4] = res;
    float4 o = ((float4*)(outp + off))[k4];
    o.x += res.x * (1.f / 3.f); o.y += res.y * (1.f / 3.f);
    o.z += res.z * (1.f / 3.f); o.w += res.w * (1.f / 3.f);
    ((float4*)(outp + off))[k4] = o;
}

// buf[row] = buf[row] @ W, in place, 16 rows/block (covers 3 contiguous types)
__global__ void k_mm(float* __restrict__ buf, const float* __restrict__ W, int N) {
    __shared__ float4 sW4[64 * 16];
    __shared__ float srow[16][68];
    int tid = threadIdx.x;
    int ty = tid >> 4, k4 = tid & 15;
    for (int i = tid; i < 1024; i += 256) sW4[i] = ((const float4*)W)[i];
    int r = blockIdx.x * 16 + ty;
    if (r < N) {
        float4 v = ((const float4*)(buf + (size_t)r * DC))[k4];
        srow[ty][k4 * 4 + 0] = v.x;
        srow[ty][k4 * 4 + 1] = v.y;
        srow[ty][k4 * 4 + 2] = v.z;
        srow[ty][k4 * 4 + 3] = v.w;
    }
    __syncthreads();
    if (r >= N) return;
    float4 a = make_float4(0.f, 0.f, 0.f, 0.f);
#pragma unroll
    for (int d = 0; d < 64; d++) {
        float4 w4 = sW4[d * 16 + k4];
        float s = srow[ty][d];
        a.x += s * w4.x; a.y += s * w4.y; a.z += s * w4.z; a.w += s * w4.w;
    }
    ((float4*)(buf + (size_t)r * DC))[k4] = a;
}

// ---------------- host orchestration ---------------------------------------
extern "C" void kernel_launch(void* const* d_in, const int* in_sizes, int n_in,
                              void* d_out, int out_size) {
    const float* user_emb = (const float*)d_in[0];
    const float* item_emb = (const float*)d_in[1];
    const float* Ein[3] = {(const float*)d_in[2], (const float*)d_in[3], (const float*)d_in[4]};
    const float* nodeW = (const float*)d_in[5];
    const float* edgeW = (const float*)d_in[6];
    const int* Ua[3] = {(const int*)d_in[7], (const int*)d_in[9], (const int*)d_in[11]};
    const int* Va[3] = {(const int*)d_in[8], (const int*)d_in[10], (const int*)d_in[12]};
    float* out = (float*)d_out;
    float* outS = out;
    float* outD = out + (size_t)NUC * DC;

    float *srcA, *srcB, *dstA, *dstB, *aggU, *aggV, *se, *de;
    float *degU, *degV, *rsU, *rsV;
    int *cntU, *cntV, *rowU, *rowV, *curU, *curV;
    int2 *adjU, *adjV;
    cudaGetSymbolAddress((void**)&srcA, g_srcA);
    cudaGetSymbolAddress((void**)&srcB, g_srcB);
    cudaGetSymbolAddress((void**)&dstA, g_dstA);
    cudaGetSymbolAddress((void**)&dstB, g_dstB);
    cudaGetSymbolAddress((void**)&aggU, g_aggU);
    cudaGetSymbolAddress((void**)&aggV, g_aggV);
    cudaGetSymbolAddress((void**)&se, g_se);
    cudaGetSymbolAddress((void**)&de, g_de);
    cudaGetSymbolAddress((void**)&cntU, g_cntU);
    cudaGetSymbolAddress((void**)&cntV, g_cntV);
    cudaGetSymbolAddress((void**)&rowU, g_rowU);
    cudaGetSymbolAddress((void**)&rowV, g_rowV);
    cudaGetSymbolAddress((void**)&curU, g_curU);
    cudaGetSymbolAddress((void**)&curV, g_curV);
    cudaGetSymbolAddress((void**)&degU, g_degU);
    cudaGetSymbolAddress((void**)&degV, g_degV);
    cudaGetSymbolAddress((void**)&rsU, g_rsU);
    cudaGetSymbolAddress((void**)&rsV, g_rsV);
    cudaGetSymbolAddress((void**)&adjU, g_adjU);
    cudaGetSymbolAddress((void**)&adjV, g_adjV);

    const int Ecnt[3] = {EBC, ECC, EPC};
    const size_t EOFF[3] = {0, EBC, EBC + ECC};
    const float Asc = 0.0045f, Bsc = 0.0045f;
    const float* Wn0 = nodeW;
    const float* Wn1 = nodeW + (size_t)DC * DC;
    const float* We0 = edgeW;

    // init node features + output accumulators (out pre-scaled by 1/3)
    k_init<<<(NUC * DC / 4 + 255) / 256, 256>>>((const float4*)user_emb, Asc,
                                                (float4*)srcA, (float4*)outS, NUC * DC / 4);
    k_init<<<(NIC * DC / 4 + 255) / 256, 256>>>((const float4*)item_emb, Asc,
                                                (float4*)dstA, (float4*)outD, NIC * DC / 4);

    // CSR build: histogram -> degrees/norms -> scan -> fill
    cudaMemsetAsync(cntU, 0, 3 * NUC * sizeof(int));
    cudaMemsetAsync(cntV, 0, 3 * NIC * sizeof(int));
    for (int t = 0; t < 3; t++)
        k_hist<<<(Ecnt[t] + 255) / 256, 256>>>(Ua[t], Va[t], Ecnt[t],
                                               cntU + t * NUC, cntV + t * NIC);
    k_deg<<<(3 * NUC + 255) / 256, 256>>>(cntU, degU, rsU, 3 * NUC);
    k_deg<<<(3 * NIC + 255) / 256, 256>>>(cntV, degV, rsV, 3 * NIC);
    k_scan6<<<6, 1024>>>(cntU, cntV, rowU, rowV, curU, curV);
    for (int t = 0; t < 3; t++)
        k_fill<<<(Ecnt[t] + 255) / 256, 256>>>(Ua[t], Va[t], Ecnt[t],
                                               curU + t * NUC, curV + t * NIC,
                                               adjU + EOFF[t], adjV + EOFF[t]);

    // ---------------- layer 0: gather from input edge stream ----------------
    for (int t = 0; t < 3; t++) {
        k_gather_l0<<<(NUC * 32 + 255) / 256, 256>>>(
            adjU + EOFF[t], rowU + t * (NUC + 1), Ein[t], Bsc,
            dstA, rsV + t * NIC,
            aggU + (size_t)t * NUC * DC, se + (size_t)t * NUC * DC, NUC);
        k_gather_l0<<<(NIC * 32 + 255) / 256, 256>>>(
            adjV + EOFF[t], rowV + t * (NIC + 1), Ein[t], Bsc,
            srcA, rsU + t * NUC,
            aggV + (size_t)t * NIC * DC, de + (size_t)t * NIC * DC, NIC);
    }
    k_gconv3<<<(NUC + 15) / 16, 256>>>(aggU, (size_t)NUC * DC, Wn0, rsU, NUC,
                                       srcB, outS, NUC, 1);
    k_gconv3<<<(NIC + 15) / 16, 256>>>(aggV, (size_t)NIC * DC, Wn0, rsV, NIC,
                                       dstB, outD, NIC, 1);
    // hoisted update_edge matmuls: se <- se@We0 (3 types), de <- de@We0
    k_mm<<<(3 * NUC + 15) / 16, 256>>>(se, We0, 3 * NUC);
    k_mm<<<(3 * NIC + 15) / 16, 256>>>(de, We0, 3 * NIC);

    // ---------------- layer 1: edge features recomputed on the fly -----------
    for (int t = 0; t < 3; t++) {
        k_gather_l1<<<(NUC * 32 + 255) / 256, 256>>>(
            adjU + EOFF[t], rowU + t * (NUC + 1),
            se + (size_t)t * NUC * DC, de + (size_t)t * NIC * DC,
            degU + t * NUC, degV + t * NIC,
            dstB, rsV + t * NIC,
            aggU + (size_t)t * NUC * DC, NUC);
        k_gather_l1<<<(NIC * 32 + 255) / 256, 256>>>(
            adjV + EOFF[t], rowV + t * (NIC + 1),
            de + (size_t)t * NIC * DC, se + (size_t)t * NUC * DC,
            degV + t * NIC, degU + t * NUC,
            srcB, rsU + t * NUC,
            aggV + (size_t)t * NIC * DC, NIC);
    }
    k_gconv3<<<(NUC + 15) / 16, 256>>>(aggU, (size_t)NUC * DC, Wn1, rsU, NUC,
                                       nullptr, outS, NUC, 0);
    k_gconv3<<<(NIC + 15) / 16, 256>>>(aggV, (size_t)NIC * DC, Wn1, rsV, NIC,
                                       nullptr, outD, NIC, 0);
}

// round 7
// speedup vs baseline: 2.2517x; 1.0683x over previous
#include <cuda_runtime.h>
#include <cstddef>

#define NUC 100000
#define NIC 50000
#define DC 64
#define EBC 500000
#define ECC 1000000
#define EPC 2000000
#define ETOT (EBC + ECC + EPC)
#define WPB 8     // warps per block
#define NPW 8     // nodes per warp

// ---------------- scratch (device globals; no allocation allowed) ----------
__device__ float g_srcB[NUC * DC];
__device__ float g_dstB[NIC * DC];
__device__ float g_se[3][NUC * DC];   // layer-0 (sum_e w) @ We, u-side
__device__ float g_de[3][NIC * DC];   // layer-0 (sum_e w) @ We, v-side
__device__ int g_cntU[3 * NUC];
__device__ int g_cntV[3 * NIC];
__device__ int g_rowU[3 * (NUC + 1)];
__device__ int g_rowV[3 * (NIC + 1)];
__device__ int g_curU[3 * NUC];
__device__ int g_curV[3 * NIC];
__device__ float g_degU[3 * NUC];
__device__ float g_degV[3 * NIC];
__device__ float g_rsU[3 * NUC];
__device__ float g_rsV[3 * NIC];
__device__ int2 g_adjU[ETOT];   // {edge id, opposite node}
__device__ int2 g_adjV[ETOT];

__device__ __forceinline__ float lk(float x) { return x >= 0.f ? x : 0.01f * x; }

// ---------------- setup kernels --------------------------------------------

// out = in * s / 3 (output accumulator init, pre-scaled by final 1/(L+1))
__global__ void k_init(const float4* __restrict__ in, float s,
                       float4* __restrict__ out, int n4) {
    int i = blockIdx.x * blockDim.x + threadIdx.x;
    if (i < n4) {
        float4 v = in[i];
        out[i] = make_float4(v.x * s, v.y * s, v.z * s, v.w * s);
    }
}

__global__ void k_hist(const int* __restrict__ U, const int* __restrict__ V, int E,
                       int* __restrict__ cU, int* __restrict__ cV) {
    int i = blockIdx.x * blockDim.x + threadIdx.x;
    if (i < E) {
        atomicAdd(cU + U[i], 1);
        atomicAdd(cV + V[i], 1);
    }
}

__global__ void k_deg(const int* __restrict__ cnt, float* __restrict__ deg,
                      float* __restrict__ rs, int n) {
    int i = blockIdx.x * blockDim.x + threadIdx.x;
    if (i < n) {
        float d = (float)(cnt[i] < 1 ? 1 : cnt[i]);
        deg[i] = d;
        rs[i] = rsqrtf(d);
    }
}

// 6 blocks: block b handles (side=b/3, type=b%3). Exclusive scan of counts.
__global__ void k_scan6(const int* __restrict__ cntU, const int* __restrict__ cntV,
                        int* __restrict__ rowU, int* __restrict__ rowV,
                        int* __restrict__ curU, int* __restrict__ curV) {
    __shared__ int ssum[1024];
    int b = blockIdx.x, side = b / 3, t = b % 3;
    const int* cnt; int* row; int* cur; int n;
    if (side == 0) { n = NUC; cnt = cntU + t * NUC; row = rowU + t * (NUC + 1); cur = curU + t * NUC; }
    else           { n = NIC; cnt = cntV + t * NIC; row = rowV + t * (NIC + 1); cur = curV + t * NIC; }
    int tid = threadIdx.x;
    int chunk = (n + 1023) / 1024;
    int lo = tid * chunk; if (lo > n) lo = n;
    int hi = lo + chunk; if (hi > n) hi = n;
    int s = 0;
    for (int i = lo; i < hi; i++) s += cnt[i];
    ssum[tid] = s;
    __syncthreads();
    for (int off = 1; off < 1024; off <<= 1) {
        int v = (tid >= off) ? ssum[tid - off] : 0;
        __syncthreads();
        ssum[tid] += v;
        __syncthreads();
    }
    int run = (tid == 0) ? 0 : ssum[tid - 1];
    for (int i = lo; i < hi; i++) {
        row[i] = run; cur[i] = run;
        run += cnt[i];
    }
    if (hi == n) row[n] = run;
}

__global__ void k_fill(const int* __restrict__ U, const int* __restrict__ V, int E,
                       int* __restrict__ cU, int* __restrict__ cV,
                       int2* __restrict__ adjU, int2* __restrict__ adjV) {
    int e = blockIdx.x * blockDim.x + threadIdx.x;
    if (e < E) {
        int u = U[e], v = V[e];
        int pu = atomicAdd(cU + u, 1);
        adjU[pu] = make_int2(e, v);
        int pv = atomicAdd(cV + v, 1);
        adjV[pv] = make_int2(e, u);
    }
}

// ---------------- layer 0: gather + fused dual matmul -----------------------
// gridDim.y = edge type t. Per node: warp gathers agg = sum_e opp*rs*A*w and
// b = sum_e w (w = B*edge_feat). Then half 0 computes agg@Wn (gconv epilogue,
// -> atomic accumulate into nxt & out), half 1 computes b@We (-> se store).
__global__ void __launch_bounds__(WPB * 32) k_l0(
        const float* __restrict__ e0, const float* __restrict__ e1,
        const float* __restrict__ e2,
        const int2* __restrict__ adjAll, const int* __restrict__ rowAll,
        int rowStride,
        const float* __restrict__ oppEmb, float oppScale,
        const float* __restrict__ rsOppAll, int nOpp,
        const float* __restrict__ rsMyAll,
        const float* __restrict__ Wn, const float* __restrict__ We,
        float* __restrict__ nxt, float* __restrict__ seOut,
        float* __restrict__ outp, int n) {
    int t = blockIdx.y;
    const float* ew = (t == 0) ? e0 : (t == 1 ? e1 : e2);
    size_t eoff = (t > 0 ? (size_t)EBC : 0) + (t > 1 ? (size_t)ECC : 0);
    const int2* adj = adjAll + eoff;
    const int* row = rowAll + t * rowStride;
    const float* rsOpp = rsOppAll + t * nOpp;
    const float* rsMy = rsMyAll + t * n;
    float* se = seOut + (size_t)t * n * DC;
    float wgt = (t == 0) ? 1.f : (t == 1 ? 0.5f : 0.25f);
    const float Bsc = 0.0045f;

    __shared__ float4 sWn[64 * 16];
    __shared__ float4 sWe[64 * 16];
    __shared__ float4 wrow4[WPB][34];   // a: [0..15], b: [17..32] (pad breaks bank clash)

    int tid = threadIdx.x;
    for (int i = tid; i < 1024; i += WPB * 32) {
        sWn[i] = ((const float4*)Wn)[i];
        sWe[i] = ((const float4*)We)[i];
    }
    __syncthreads();

    int wid = tid >> 5, lane = tid & 31, l16 = lane & 15, half = lane >> 4;
    int nodeBase = (blockIdx.x * WPB + wid) * NPW;

    for (int nd = 0; nd < NPW; nd++) {
        int node = nodeBase + nd;
        if (node >= n) break;   // warp-uniform
        int s0 = row[node], s1 = row[node + 1];
        float4 a = make_float4(0.f, 0.f, 0.f, 0.f);
        float4 b = make_float4(0.f, 0.f, 0.f, 0.f);
#pragma unroll 2
        for (int i = s0 + half; i < s1; i += 2) {
            int2 ad = __ldg(adj + i);
            float4 w = __ldg((const float4*)(ew + (size_t)ad.x * DC) + l16);
            w.x *= Bsc; w.y *= Bsc; w.z *= Bsc; w.w *= Bsc;
            float r = __ldg(rsOpp + ad.y) * oppScale;
            float4 f = __ldg((const float4*)(oppEmb + (size_t)ad.y * DC) + l16);
            b.x += w.x; b.y += w.y; b.z += w.z; b.w += w.w;
            a.x += f.x * r * w.x; a.y += f.y * r * w.y;
            a.z += f.z * r * w.z; a.w += f.w * r * w.w;
        }
        a.x += __shfl_xor_sync(0xffffffffu, a.x, 16);
        a.y += __shfl_xor_sync(0xffffffffu, a.y, 16);
        a.z += __shfl_xor_sync(0xffffffffu, a.z, 16);
        a.w += __shfl_xor_sync(0xffffffffu, a.w, 16);
        b.x += __shfl_xor_sync(0xffffffffu, b.x, 16);
        b.y += __shfl_xor_sync(0xffffffffu, b.y, 16);
        b.z += __shfl_xor_sync(0xffffffffu, b.z, 16);
        b.w += __shfl_xor_sync(0xffffffffu, b.w, 16);
        if (half == 0) wrow4[wid][l16] = a;
        else           wrow4[wid][17 + l16] = b;
        __syncwarp();

        // dual matmul: half 0 -> a @ Wn ; half 1 -> b @ We
        const float* rsel = (const float*)&wrow4[wid][0] + (half ? 68 : 0);
        const float4* Wsel = half ? sWe : sWn;
        float4 acc = make_float4(0.f, 0.f, 0.f, 0.f);
#pragma unroll
        for (int d = 0; d < 64; d++) {
            float s = rsel[d];
            float4 w4 = Wsel[d * 16 + l16];
            acc.x += s * w4.x; acc.y += s * w4.y;
            acc.z += s * w4.z; acc.w += s * w4.w;
        }
        __syncwarp();
        if (half == 0) {
            float rsn = rsMy[node];
            float4 res;
            res.x = lk(acc.x * rsn) * wgt;
            res.y = lk(acc.y * rsn) * wgt;
            res.z = lk(acc.z * rsn) * wgt;
            res.w = lk(acc.w * rsn) * wgt;
            size_t off = (size_t)node * DC + l16 * 4;
            atomicAdd((float4*)(nxt + off), res);
            float4 ro = make_float4(res.x * (1.f / 3.f), res.y * (1.f / 3.f),
                                    res.z * (1.f / 3.f), res.w * (1.f / 3.f));
            atomicAdd((float4*)(outp + off), ro);
        } else {
            ((float4*)(se + (size_t)node * DC))[l16] = acc;
        }
    }
}

// ---------------- layer 1: on-the-fly edge weights + fused matmul -----------
// w_e = leaky((seW[my] + deW[opp]) / (deg[my] + deg[opp])); agg = sum f*r*w.
// Matmul split across halves (32 d each) then shfl-combined.
__global__ void __launch_bounds__(WPB * 32) k_l1(
        const int2* __restrict__ adjAll, const int* __restrict__ rowAll,
        int rowStride,
        const float* __restrict__ myDeWAll, const float* __restrict__ oppDeWAll,
        const float* __restrict__ myDegAll, const float* __restrict__ oppDegAll,
        const float* __restrict__ oppF, const float* __restrict__ rsOppAll, int nOpp,
        const float* __restrict__ rsMyAll,
        const float* __restrict__ Wn, float* __restrict__ outp, int n) {
    int t = blockIdx.y;
    size_t eoff = (t > 0 ? (size_t)EBC : 0) + (t > 1 ? (size_t)ECC : 0);
    const int2* adj = adjAll + eoff;
    const int* row = rowAll + t * rowStride;
    const float* myDeW = myDeWAll + (size_t)t * n * DC;
    const float* oppDeW = oppDeWAll + (size_t)t * nOpp * DC;
    const float* myDeg = myDegAll + t * n;
    const float* oppDeg = oppDegAll + t * nOpp;
    const float* rsOpp = rsOppAll + t * nOpp;
    const float* rsMy = rsMyAll + t * n;
    float wgt = (t == 0) ? 1.f : (t == 1 ? 0.5f : 0.25f);

    __shared__ float4 sWn[64 * 16];
    __shared__ float wrow[WPB][66];   // a[d] at index d + (d>>5) (pad at 32)

    int tid = threadIdx.x;
    for (int i = tid; i < 1024; i += WPB * 32) sWn[i] = ((const float4*)Wn)[i];
    __syncthreads();

    int wid = tid >> 5, lane = tid & 31, l16 = lane & 15, half = lane >> 4;
    int nodeBase = (blockIdx.x * WPB + wid) * NPW;

    for (int nd = 0; nd < NPW; nd++) {
        int node = nodeBase + nd;
        if (node >= n) break;
        int s0 = row[node], s1 = row[node + 1];
        float md = myDeg[node];
        float4 m = __ldg((const float4*)(myDeW + (size_t)node * DC) + l16);
        float4 a = make_float4(0.f, 0.f, 0.f, 0.f);
#pragma unroll 2
        for (int i = s0 + half; i < s1; i += 2) {
            int2 ad = __ldg(adj + i);
            float od = __ldg(oppDeg + ad.y);
            float s = 1.f / (md + od);
            float4 o = __ldg((const float4*)(oppDeW + (size_t)ad.y * DC) + l16);
            float r = __ldg(rsOpp + ad.y);
            float4 f = __ldg((const float4*)(oppF + (size_t)ad.y * DC) + l16);
            float wx = lk((m.x + o.x) * s);
            float wy = lk((m.y + o.y) * s);
            float wz = lk((m.z + o.z) * s);
            float ww = lk((m.w + o.w) * s);
            a.x += f.x * r * wx; a.y += f.y * r * wy;
            a.z += f.z * r * wz; a.w += f.w * r * ww;
        }
        a.x += __shfl_xor_sync(0xffffffffu, a.x, 16);
        a.y += __shfl_xor_sync(0xffffffffu, a.y, 16);
        a.z += __shfl_xor_sync(0xffffffffu, a.z, 16);
        a.w += __shfl_xor_sync(0xffffffffu, a.w, 16);
        if (half == 0) {
            int p = l16 * 4;
            wrow[wid][p + (p >> 5)] = a.x;
            wrow[wid][p + 1 + ((p + 1) >> 5)] = a.y;
            wrow[wid][p + 2 + ((p + 2) >> 5)] = a.z;
            wrow[wid][p + 3 + ((p + 3) >> 5)] = a.w;
        }
        __syncwarp();

        const float* wr = &wrow[wid][half * 33];
        const float4* Wh = sWn + half * 32 * 16;
        float4 acc = make_float4(0.f, 0.f, 0.f, 0.f);
#pragma unroll
        for (int d2 = 0; d2 < 32; d2++) {
            float s = wr[d2];
            float4 w4 = Wh[d2 * 16 + l16];
            acc.x += s * w4.x; acc.y += s * w4.y;
            acc.z += s * w4.z; acc.w += s * w4.w;
        }
        acc.x += __shfl_xor_sync(0xffffffffu, acc.x, 16);
        acc.y += __shfl_xor_sync(0xffffffffu, acc.y, 16);
        acc.z += __shfl_xor_sync(0xffffffffu, acc.z, 16);
        acc.w += __shfl_xor_sync(0xffffffffu, acc.w, 16);
        __syncwarp();
        if (half == 0) {
            float rsn = rsMy[node];
            float c = wgt * (1.f / 3.f);
            float4 ro;
            ro.x = lk(acc.x * rsn) * c;
            ro.y = lk(acc.y * rsn) * c;
            ro.z = lk(acc.z * rsn) * c;
            ro.w = lk(acc.w * rsn) * c;
            atomicAdd((float4*)(outp + (size_t)node * DC + l16 * 4), ro);
        }
    }
}

// ---------------- host orchestration ---------------------------------------
extern "C" void kernel_launch(void* const* d_in, const int* in_sizes, int n_in,
                              void* d_out, int out_size) {
    const float* user_emb = (const float*)d_in[0];
    const float* item_emb = (const float*)d_in[1];
    const float* e0 = (const float*)d_in[2];
    const float* e1 = (const float*)d_in[3];
    const float* e2 = (const float*)d_in[4];
    const float* nodeW = (const float*)d_in[5];
    const float* edgeW = (const float*)d_in[6];
    const int* Ua[3] = {(const int*)d_in[7], (const int*)d_in[9], (const int*)d_in[11]};
    const int* Va[3] = {(const int*)d_in[8], (const int*)d_in[10], (const int*)d_in[12]};
    float* out = (float*)d_out;
    float* outS = out;
    float* outD = out + (size_t)NUC * DC;

    float *srcB, *dstB, *se, *de, *degU, *degV, *rsU, *rsV;
    int *cntU, *cntV, *rowU, *rowV, *curU, *curV;
    int2 *adjU, *adjV;
    cudaGetSymbolAddress((void**)&srcB, g_srcB);
    cudaGetSymbolAddress((void**)&dstB, g_dstB);
    cudaGetSymbolAddress((void**)&se, g_se);
    cudaGetSymbolAddress((void**)&de, g_de);
    cudaGetSymbolAddress((void**)&cntU, g_cntU);
    cudaGetSymbolAddress((void**)&cntV, g_cntV);
    cudaGetSymbolAddress((void**)&rowU, g_rowU);
    cudaGetSymbolAddress((void**)&rowV, g_rowV);
    cudaGetSymbolAddress((void**)&curU, g_curU);
    cudaGetSymbolAddress((void**)&curV, g_curV);
    cudaGetSymbolAddress((void**)&degU, g_degU);
    cudaGetSymbolAddress((void**)&degV, g_degV);
    cudaGetSymbolAddress((void**)&rsU, g_rsU);
    cudaGetSymbolAddress((void**)&rsV, g_rsV);
    cudaGetSymbolAddress((void**)&adjU, g_adjU);
    cudaGetSymbolAddress((void**)&adjV, g_adjV);

    const int Ecnt[3] = {EBC, ECC, EPC};
    const float Asc = 0.0045f;
    const float* Wn0 = nodeW;
    const float* Wn1 = nodeW + (size_t)DC * DC;
    const float* We0 = edgeW;

    // output accumulator init (pre-scaled by 1/3) + zero nxt buffers
    k_init<<<(NUC * DC / 4 + 255) / 256, 256>>>((const float4*)user_emb,
                                                Asc / 3.f, (float4*)outS, NUC * DC / 4);
    k_init<<<(NIC * DC / 4 + 255) / 256, 256>>>((const float4*)item_emb,
                                                Asc / 3.f, (float4*)outD, NIC * DC / 4);
    cudaMemsetAsync(srcB, 0, (size_t)NUC * DC * sizeof(float));
    cudaMemsetAsync(dstB, 0, (size_t)NIC * DC * sizeof(float));

    // CSR build
    cudaMemsetAsync(cntU, 0, 3 * NUC * sizeof(int));
    cudaMemsetAsync(cntV, 0, 3 * NIC * sizeof(int));
    for (int t = 0; t < 3; t++)
        k_hist<<<(Ecnt[t] + 255) / 256, 256>>>(Ua[t], Va[t], Ecnt[t],
                                               cntU + t * NUC, cntV + t * NIC);
    k_deg<<<(3 * NUC + 255) / 256, 256>>>(cntU, degU, rsU, 3 * NUC);
    k_deg<<<(3 * NIC + 255) / 256, 256>>>(cntV, degV, rsV, 3 * NIC);
    k_scan6<<<6, 1024>>>(cntU, cntV, rowU, rowV, curU, curV);
    {
        size_t eo = 0;
        for (int t = 0; t < 3; t++) {
            k_fill<<<(Ecnt[t] + 255) / 256, 256>>>(Ua[t], Va[t], Ecnt[t],
                                                   curU + t * NUC, curV + t * NIC,
                                                   adjU + eo, adjV + eo);
            eo += Ecnt[t];
        }
    }

    // layer 0 (3 types concurrent via gridDim.y)
    {
        dim3 gu((NUC + WPB * NPW - 1) / (WPB * NPW), 3);
        dim3 gv((NIC + WPB * NPW - 1) / (WPB * NPW), 3);
        k_l0<<<gu, WPB * 32>>>(e0, e1, e2, adjU, rowU, NUC + 1,
                               item_emb, Asc, rsV, NIC, rsU,
                               Wn0, We0, srcB, se, outS, NUC);
        k_l0<<<gv, WPB * 32>>>(e0, e1, e2, adjV, rowV, NIC + 1,
                               user_emb, Asc, rsU, NUC, rsV,
                               Wn0, We0, dstB, de, outD, NIC);
    }

    // layer 1 (edge features recomputed on the fly; output accumulate only)
    {
        dim3 gu((NUC + WPB * NPW - 1) / (WPB * NPW), 3);
        dim3 gv((NIC + WPB * NPW - 1) / (WPB * NPW), 3);
        k_l1<<<gu, WPB * 32>>>(adjU, rowU, NUC + 1, se, de, degU, degV,
                               dstB, rsV, NIC, rsU, Wn1, outS, NUC);
        k_l1<<<gv, WPB * 32>>>(adjV, rowV, NIC + 1, de, se, degV, degU,
                               srcB, rsU, NUC, rsV, Wn1, outD, NIC);
    }
}